// round 6
// baseline (speedup 1.0000x reference)
#include <cuda_runtime.h>
#include <math.h>

#define S_LEN 2048
#define BATCH 2
#define DIM   1024
#define NHEAD 16
#define HDIM  64
#define TDIM  1032
#define ROWS  (S_LEN*BATCH)   // 4096

// Scratch (static device allocations are the sanctioned path)
__device__ float g_w[3][DIM*DIM];        // conv-produced weights (+conv bias folded)
__device__ float g_qkv[3][ROWS*DIM];     // projected q,k,v

// ---------------------------------------------------------------------------
// Kernel 1: 9x9 VALID conv over template -> three 1024x1024 weight matrices.
// One shared template tile feeds all three filters.
// ---------------------------------------------------------------------------
__global__ void conv_kernel(const float* __restrict__ tmpl,
                            const float* __restrict__ cw0, const float* __restrict__ cb0,
                            const float* __restrict__ cw1, const float* __restrict__ cb1,
                            const float* __restrict__ cw2, const float* __restrict__ cb2) {
    __shared__ float sm[40][40];
    __shared__ float scw[3][81];
    const int tid = threadIdx.y * 32 + threadIdx.x;
    if (tid < 81) {
        scw[0][tid] = cw0[tid];
        scw[1][tid] = cw1[tid];
        scw[2][tid] = cw2[tid];
    }
    const int i0 = blockIdx.x * 32;   // input-col tile
    const int o0 = blockIdx.y * 32;   // output-row tile
    for (int idx = tid; idx < 40*40; idx += 256) {
        int r = idx / 40, c = idx % 40;
        sm[r][c] = tmpl[(size_t)(o0 + r) * TDIM + (i0 + c)];
    }
    __syncthreads();

    const int tx = threadIdx.x, ty = threadIdx.y;
    float acc0[4] = {0.f,0.f,0.f,0.f};
    float acc1[4] = {0.f,0.f,0.f,0.f};
    float acc2[4] = {0.f,0.f,0.f,0.f};
    #pragma unroll
    for (int u = 0; u < 9; u++) {
        #pragma unroll
        for (int v = 0; v < 9; v++) {
            const float w0 = scw[0][u*9+v];
            const float w1 = scw[1][u*9+v];
            const float w2 = scw[2][u*9+v];
            #pragma unroll
            for (int r = 0; r < 4; r++) {
                float t = sm[ty*4 + r + u][tx + v];
                acc0[r] += t * w0;
                acc1[r] += t * w1;
                acc2[r] += t * w2;
            }
        }
    }
    const float b0 = cb0[0], b1 = cb1[0], b2 = cb2[0];
    #pragma unroll
    for (int r = 0; r < 4; r++) {
        const size_t off = (size_t)(o0 + ty*4 + r) * DIM + i0 + tx;
        g_w[0][off] = acc0[r] + b0;
        g_w[1][off] = acc1[r] + b1;
        g_w[2][off] = acc2[r] + b2;
    }
}

// ---------------------------------------------------------------------------
// Kernel 2: projection GEMM (NT): Out[r,o] = sum_k A[r,k]*W[o,k] + lin_b[o].
// 64x64 block tile, BK=16, 256 threads, 4x4 micro-tile per thread.
// blockIdx.z selects q/k/v.
// ---------------------------------------------------------------------------
__global__ void proj_kernel(const float* __restrict__ qin, const float* __restrict__ kin,
                            const float* __restrict__ vin,
                            const float* __restrict__ bq, const float* __restrict__ bk,
                            const float* __restrict__ bv) {
    const int m = blockIdx.z;
    const float* __restrict__ A    = (m == 0) ? qin : (m == 1) ? kin : vin;
    const float* __restrict__ bias = (m == 0) ? bq  : (m == 1) ? bk  : bv;
    const float* __restrict__ W    = g_w[m];
    float* __restrict__ Out        = g_qkv[m];

    __shared__ float As[16][64];
    __shared__ float Ws[16][64];

    const int tid  = threadIdx.y * 16 + threadIdx.x;
    const int r0   = blockIdx.y * 64;
    const int c0   = blockIdx.x * 64;
    const int lrow = tid >> 2;        // 0..63
    const int lk   = (tid & 3) * 4;   // 0,4,8,12

    float c[4][4] = {};

    for (int kt = 0; kt < DIM; kt += 16) {
        const float4 av = *(const float4*)&A[(size_t)(r0 + lrow) * DIM + kt + lk];
        const float4 wv = *(const float4*)&W[(size_t)(c0 + lrow) * DIM + kt + lk];
        __syncthreads();
        As[lk+0][lrow] = av.x; As[lk+1][lrow] = av.y;
        As[lk+2][lrow] = av.z; As[lk+3][lrow] = av.w;
        Ws[lk+0][lrow] = wv.x; Ws[lk+1][lrow] = wv.y;
        Ws[lk+2][lrow] = wv.z; Ws[lk+3][lrow] = wv.w;
        __syncthreads();
        #pragma unroll
        for (int kk = 0; kk < 16; kk++) {
            const float4 a = *(const float4*)&As[kk][threadIdx.y * 4];
            const float4 b = *(const float4*)&Ws[kk][threadIdx.x * 4];
            c[0][0] += a.x*b.x; c[0][1] += a.x*b.y; c[0][2] += a.x*b.z; c[0][3] += a.x*b.w;
            c[1][0] += a.y*b.x; c[1][1] += a.y*b.y; c[1][2] += a.y*b.z; c[1][3] += a.y*b.w;
            c[2][0] += a.z*b.x; c[2][1] += a.z*b.y; c[2][2] += a.z*b.z; c[2][3] += a.z*b.w;
            c[3][0] += a.w*b.x; c[3][1] += a.w*b.y; c[3][2] += a.w*b.z; c[3][3] += a.w*b.w;
        }
    }

    const int orow = r0 + threadIdx.y * 4;
    const int ocol = c0 + threadIdx.x * 4;
    const float4 bb = *(const float4*)&bias[ocol];
    #pragma unroll
    for (int i = 0; i < 4; i++) {
        float4 res;
        res.x = c[i][0] + bb.x;
        res.y = c[i][1] + bb.y;
        res.z = c[i][2] + bb.z;
        res.w = c[i][3] + bb.w;
        *(float4*)&Out[(size_t)(orow + i) * DIM + ocol] = res;
    }
}

// ---------------------------------------------------------------------------
// Kernel 3: flash attention, fp32. One thread = one query row; 128 rows/block.
// KV streamed in 64-row tiles through shared memory; online softmax.
// Scores are near-one-hot (sigma~207) so __expf precision is more than enough.
// ---------------------------------------------------------------------------
__global__ void __launch_bounds__(128) attn_kernel(float* __restrict__ out) {
    const float* __restrict__ Q  = g_qkv[0];
    const float* __restrict__ Kp = g_qkv[1];
    const float* __restrict__ Vp = g_qkv[2];

    __shared__ float Ks[64][64];
    __shared__ float Vs[64][64];

    const int tid = threadIdx.x;
    const int qt  = blockIdx.x;           // 0..15  (128 q rows each)
    const int bh  = blockIdx.y;           // 0..31
    const int b   = bh & 1;
    const int h   = bh >> 1;

    const int qrow = qt * 128 + tid;
    const float* qptr = Q + ((size_t)(qrow * BATCH + b)) * DIM + h * HDIM;

    float qreg[64];
    #pragma unroll
    for (int d4 = 0; d4 < 16; d4++) {
        float4 t = *(const float4*)(qptr + d4 * 4);
        qreg[d4*4+0] = t.x * 0.125f;   // fold 1/sqrt(64) into q
        qreg[d4*4+1] = t.y * 0.125f;
        qreg[d4*4+2] = t.z * 0.125f;
        qreg[d4*4+3] = t.w * 0.125f;
    }
    float o[64];
    #pragma unroll
    for (int d = 0; d < 64; d++) o[d] = 0.f;
    float mval = -1e30f, l = 0.f;

    const size_t kvbase = (size_t)b * DIM + (size_t)h * HDIM;
    const size_t rstride = (size_t)BATCH * DIM;

    for (int kt = 0; kt < S_LEN / 64; kt++) {
        __syncthreads();
        const int s0 = kt * 64;
        for (int idx = tid; idx < 64 * 16; idx += 128) {
            const int j  = idx >> 4;
            const int d4 = (idx & 15) << 2;
            const size_t off = (size_t)(s0 + j) * rstride + kvbase + d4;
            *(float4*)&Ks[j][d4] = *(const float4*)(Kp + off);
            *(float4*)&Vs[j][d4] = *(const float4*)(Vp + off);
        }
        __syncthreads();

        #pragma unroll 1
        for (int ch = 0; ch < 4; ch++) {
            float s[16];
            #pragma unroll
            for (int jj = 0; jj < 16; jj++) {
                const int j = ch * 16 + jj;
                float acc = 0.f;
                #pragma unroll
                for (int d4 = 0; d4 < 16; d4++) {
                    const float4 kv = *(const float4*)&Ks[j][d4 << 2];
                    acc += qreg[d4*4+0] * kv.x;
                    acc += qreg[d4*4+1] * kv.y;
                    acc += qreg[d4*4+2] * kv.z;
                    acc += qreg[d4*4+3] * kv.w;
                }
                s[jj] = acc;
            }
            float mx = mval;
            #pragma unroll
            for (int jj = 0; jj < 16; jj++) mx = fmaxf(mx, s[jj]);
            if (mx > mval) {
                const float scale = __expf(mval - mx);
                mval = mx;
                l *= scale;
                #pragma unroll
                for (int d = 0; d < 64; d++) o[d] *= scale;
            }
            #pragma unroll
            for (int jj = 0; jj < 16; jj++) {
                const int j = ch * 16 + jj;
                const float p = __expf(s[jj] - mval);
                l += p;
                #pragma unroll
                for (int d4 = 0; d4 < 16; d4++) {
                    const float4 vv = *(const float4*)&Vs[j][d4 << 2];
                    o[d4*4+0] += p * vv.x;
                    o[d4*4+1] += p * vv.y;
                    o[d4*4+2] += p * vv.z;
                    o[d4*4+3] += p * vv.w;
                }
            }
        }
    }

    const float inv = 1.f / l;
    float* op = out + ((size_t)(qrow * BATCH + b)) * DIM + h * HDIM;
    #pragma unroll
    for (int d4 = 0; d4 < 16; d4++) {
        float4 res;
        res.x = o[d4*4+0] * inv;
        res.y = o[d4*4+1] * inv;
        res.z = o[d4*4+2] * inv;
        res.w = o[d4*4+3] * inv;
        *(float4*)(op + d4 * 4) = res;
    }
}

// ---------------------------------------------------------------------------
extern "C" void kernel_launch(void* const* d_in, const int* in_sizes, int n_in,
                              void* d_out, int out_size) {
    const float* query = (const float*)d_in[0];
    const float* key   = (const float*)d_in[1];
    const float* value = (const float*)d_in[2];
    const float* tmpl  = (const float*)d_in[3];
    const float* wq_cw = (const float*)d_in[4];
    const float* wq_cb = (const float*)d_in[5];
    const float* wq_b  = (const float*)d_in[6];
    const float* wk_cw = (const float*)d_in[7];
    const float* wk_cb = (const float*)d_in[8];
    const float* wk_b  = (const float*)d_in[9];
    const float* wv_cw = (const float*)d_in[10];
    const float* wv_cb = (const float*)d_in[11];
    const float* wv_b  = (const float*)d_in[12];
    float* out = (float*)d_out;

    conv_kernel<<<dim3(32, 32), dim3(32, 8)>>>(tmpl, wq_cw, wq_cb, wk_cw, wk_cb, wv_cw, wv_cb);
    proj_kernel<<<dim3(16, 64, 3), dim3(16, 16)>>>(query, key, value, wq_b, wk_b, wv_b);
    attn_kernel<<<dim3(16, 32), dim3(128)>>>(out);
}

// round 7
// speedup vs baseline: 1.0549x; 1.0549x over previous
#include <cuda_runtime.h>
#include <math.h>

#define S_LEN 2048
#define BATCH 2
#define DIM   1024
#define NHEAD 16
#define HDIM  64
#define TDIM  1032
#define ROWS  (S_LEN*BATCH)   // 4096

// Scratch (static device allocations are the sanctioned path)
__device__ float g_w[3][DIM*DIM];        // conv-produced weights (+conv bias folded)
__device__ float g_qkv[3][ROWS*DIM];     // projected q,k,v

// ---------------------------------------------------------------------------
// Kernel 1: 9x9 VALID conv over template -> three 1024x1024 weight matrices.
// One shared template tile feeds all three filters.
// ---------------------------------------------------------------------------
__global__ void conv_kernel(const float* __restrict__ tmpl,
                            const float* __restrict__ cw0, const float* __restrict__ cb0,
                            const float* __restrict__ cw1, const float* __restrict__ cb1,
                            const float* __restrict__ cw2, const float* __restrict__ cb2) {
    __shared__ float sm[40][40];
    __shared__ float scw[3][81];
    const int tid = threadIdx.y * 32 + threadIdx.x;
    if (tid < 81) {
        scw[0][tid] = cw0[tid];
        scw[1][tid] = cw1[tid];
        scw[2][tid] = cw2[tid];
    }
    const int i0 = blockIdx.x * 32;   // input-col tile
    const int o0 = blockIdx.y * 32;   // output-row tile
    for (int idx = tid; idx < 40*40; idx += 256) {
        int r = idx / 40, c = idx % 40;
        sm[r][c] = tmpl[(size_t)(o0 + r) * TDIM + (i0 + c)];
    }
    __syncthreads();

    const int tx = threadIdx.x, ty = threadIdx.y;
    float acc0[4] = {0.f,0.f,0.f,0.f};
    float acc1[4] = {0.f,0.f,0.f,0.f};
    float acc2[4] = {0.f,0.f,0.f,0.f};
    #pragma unroll
    for (int u = 0; u < 9; u++) {
        #pragma unroll
        for (int v = 0; v < 9; v++) {
            const float w0 = scw[0][u*9+v];
            const float w1 = scw[1][u*9+v];
            const float w2 = scw[2][u*9+v];
            #pragma unroll
            for (int r = 0; r < 4; r++) {
                float t = sm[ty*4 + r + u][tx + v];
                acc0[r] += t * w0;
                acc1[r] += t * w1;
                acc2[r] += t * w2;
            }
        }
    }
    const float b0 = cb0[0], b1 = cb1[0], b2 = cb2[0];
    #pragma unroll
    for (int r = 0; r < 4; r++) {
        const size_t off = (size_t)(o0 + ty*4 + r) * DIM + i0 + tx;
        g_w[0][off] = acc0[r] + b0;
        g_w[1][off] = acc1[r] + b1;
        g_w[2][off] = acc2[r] + b2;
    }
}

// ---------------------------------------------------------------------------
// Kernel 2: projection GEMM (NT): Out[r,o] = sum_k A[r,k]*W[o,k] + lin_b[o].
// 64x64 block tile, BK=16, 256 threads, 4x4 micro-tile per thread.
// blockIdx.z selects q/k/v.
// ---------------------------------------------------------------------------
__global__ void proj_kernel(const float* __restrict__ qin, const float* __restrict__ kin,
                            const float* __restrict__ vin,
                            const float* __restrict__ bq, const float* __restrict__ bk,
                            const float* __restrict__ bv) {
    const int m = blockIdx.z;
    const float* __restrict__ A    = (m == 0) ? qin : (m == 1) ? kin : vin;
    const float* __restrict__ bias = (m == 0) ? bq  : (m == 1) ? bk  : bv;
    const float* __restrict__ W    = g_w[m];
    float* __restrict__ Out        = g_qkv[m];

    __shared__ float As[16][64];
    __shared__ float Ws[16][64];

    const int tid  = threadIdx.y * 16 + threadIdx.x;
    const int r0   = blockIdx.y * 64;
    const int c0   = blockIdx.x * 64;
    const int lrow = tid >> 2;        // 0..63
    const int lk   = (tid & 3) * 4;   // 0,4,8,12

    float c[4][4] = {};

    for (int kt = 0; kt < DIM; kt += 16) {
        const float4 av = *(const float4*)&A[(size_t)(r0 + lrow) * DIM + kt + lk];
        const float4 wv = *(const float4*)&W[(size_t)(c0 + lrow) * DIM + kt + lk];
        __syncthreads();
        As[lk+0][lrow] = av.x; As[lk+1][lrow] = av.y;
        As[lk+2][lrow] = av.z; As[lk+3][lrow] = av.w;
        Ws[lk+0][lrow] = wv.x; Ws[lk+1][lrow] = wv.y;
        Ws[lk+2][lrow] = wv.z; Ws[lk+3][lrow] = wv.w;
        __syncthreads();
        #pragma unroll
        for (int kk = 0; kk < 16; kk++) {
            const float4 a = *(const float4*)&As[kk][threadIdx.y * 4];
            const float4 b = *(const float4*)&Ws[kk][threadIdx.x * 4];
            c[0][0] += a.x*b.x; c[0][1] += a.x*b.y; c[0][2] += a.x*b.z; c[0][3] += a.x*b.w;
            c[1][0] += a.y*b.x; c[1][1] += a.y*b.y; c[1][2] += a.y*b.z; c[1][3] += a.y*b.w;
            c[2][0] += a.z*b.x; c[2][1] += a.z*b.y; c[2][2] += a.z*b.z; c[2][3] += a.z*b.w;
            c[3][0] += a.w*b.x; c[3][1] += a.w*b.y; c[3][2] += a.w*b.z; c[3][3] += a.w*b.w;
        }
    }

    const int orow = r0 + threadIdx.y * 4;
    const int ocol = c0 + threadIdx.x * 4;
    const float4 bb = *(const float4*)&bias[ocol];
    #pragma unroll
    for (int i = 0; i < 4; i++) {
        float4 res;
        res.x = c[i][0] + bb.x;
        res.y = c[i][1] + bb.y;
        res.z = c[i][2] + bb.z;
        res.w = c[i][3] + bb.w;
        *(float4*)&Out[(size_t)(orow + i) * DIM + ocol] = res;
    }
}

// ---------------------------------------------------------------------------
// Kernel 3: flash attention, fp32. One thread = one query row; 128 rows/block.
// KV streamed in 64-row tiles through shared memory; online softmax.
// Scores are near-one-hot (sigma~207) so __expf precision is more than enough.
// ---------------------------------------------------------------------------
__global__ void __launch_bounds__(128) attn_kernel(float* __restrict__ out) {
    const float* __restrict__ Q  = g_qkv[0];
    const float* __restrict__ Kp = g_qkv[1];
    const float* __restrict__ Vp = g_qkv[2];

    __shared__ float Ks[64][64];
    __shared__ float Vs[64][64];

    const int tid = threadIdx.x;
    const int qt  = blockIdx.x;           // 0..15  (128 q rows each)
    const int bh  = blockIdx.y;           // 0..31
    const int b   = bh & 1;
    const int h   = bh >> 1;

    const int qrow = qt * 128 + tid;
    const float* qptr = Q + ((size_t)(qrow * BATCH + b)) * DIM + h * HDIM;

    float qreg[64];
    #pragma unroll
    for (int d4 = 0; d4 < 16; d4++) {
        float4 t = *(const float4*)(qptr + d4 * 4);
        qreg[d4*4+0] = t.x * 0.125f;   // fold 1/sqrt(64) into q
        qreg[d4*4+1] = t.y * 0.125f;
        qreg[d4*4+2] = t.z * 0.125f;
        qreg[d4*4+3] = t.w * 0.125f;
    }
    float o[64];
    #pragma unroll
    for (int d = 0; d < 64; d++) o[d] = 0.f;
    float mval = -1e30f, l = 0.f;

    const size_t kvbase = (size_t)b * DIM + (size_t)h * HDIM;
    const size_t rstride = (size_t)BATCH * DIM;

    for (int kt = 0; kt < S_LEN / 64; kt++) {
        __syncthreads();
        const int s0 = kt * 64;
        for (int idx = tid; idx < 64 * 16; idx += 128) {
            const int j  = idx >> 4;
            const int d4 = (idx & 15) << 2;
            const size_t off = (size_t)(s0 + j) * rstride + kvbase + d4;
            *(float4*)&Ks[j][d4] = *(const float4*)(Kp + off);
            *(float4*)&Vs[j][d4] = *(const float4*)(Vp + off);
        }
        __syncthreads();

        #pragma unroll 1
        for (int ch = 0; ch < 4; ch++) {
            float s[16];
            #pragma unroll
            for (int jj = 0; jj < 16; jj++) {
                const int j = ch * 16 + jj;
                float acc = 0.f;
                #pragma unroll
                for (int d4 = 0; d4 < 16; d4++) {
                    const float4 kv = *(const float4*)&Ks[j][d4 << 2];
                    acc += qreg[d4*4+0] * kv.x;
                    acc += qreg[d4*4+1] * kv.y;
                    acc += qreg[d4*4+2] * kv.z;
                    acc += qreg[d4*4+3] * kv.w;
                }
                s[jj] = acc;
            }
            float mx = mval;
            #pragma unroll
            for (int jj = 0; jj < 16; jj++) mx = fmaxf(mx, s[jj]);
            if (mx > mval) {
                const float scale = __expf(mval - mx);
                mval = mx;
                l *= scale;
                #pragma unroll
                for (int d = 0; d < 64; d++) o[d] *= scale;
            }
            #pragma unroll
            for (int jj = 0; jj < 16; jj++) {
                const int j = ch * 16 + jj;
                const float p = __expf(s[jj] - mval);
                l += p;
                #pragma unroll
                for (int d4 = 0; d4 < 16; d4++) {
                    const float4 vv = *(const float4*)&Vs[j][d4 << 2];
                    o[d4*4+0] += p * vv.x;
                    o[d4*4+1] += p * vv.y;
                    o[d4*4+2] += p * vv.z;
                    o[d4*4+3] += p * vv.w;
                }
            }
        }
    }

    const float inv = 1.f / l;
    float* op = out + ((size_t)(qrow * BATCH + b)) * DIM + h * HDIM;
    #pragma unroll
    for (int d4 = 0; d4 < 16; d4++) {
        float4 res;
        res.x = o[d4*4+0] * inv;
        res.y = o[d4*4+1] * inv;
        res.z = o[d4*4+2] * inv;
        res.w = o[d4*4+3] * inv;
        *(float4*)(op + d4 * 4) = res;
    }
}

// ---------------------------------------------------------------------------
extern "C" void kernel_launch(void* const* d_in, const int* in_sizes, int n_in,
                              void* d_out, int out_size) {
    const float* query = (const float*)d_in[0];
    const float* key   = (const float*)d_in[1];
    const float* value = (const float*)d_in[2];
    const float* tmpl  = (const float*)d_in[3];
    const float* wq_cw = (const float*)d_in[4];
    const float* wq_cb = (const float*)d_in[5];
    const float* wq_b  = (const float*)d_in[6];
    const float* wk_cw = (const float*)d_in[7];
    const float* wk_cb = (const float*)d_in[8];
    const float* wk_b  = (const float*)d_in[9];
    const float* wv_cw = (const float*)d_in[10];
    const float* wv_cb = (const float*)d_in[11];
    const float* wv_b  = (const float*)d_in[12];
    float* out = (float*)d_out;

    conv_kernel<<<dim3(32, 32), dim3(32, 8)>>>(tmpl, wq_cw, wq_cb, wk_cw, wk_cb, wv_cw, wv_cb);
    proj_kernel<<<dim3(16, 64, 3), dim3(16, 16)>>>(query, key, value, wq_b, wk_b, wv_b);
    attn_kernel<<<dim3(16, 32), dim3(128)>>>(out);
}

// round 8
// speedup vs baseline: 1.0556x; 1.0006x over previous
#include <cuda_runtime.h>
#include <math.h>

#define S_LEN 2048
#define BATCH 2
#define DIM   1024
#define NHEAD 16
#define HDIM  64
#define TDIM  1032
#define ROWS  (S_LEN*BATCH)   // 4096

// Scratch (static device allocations are the sanctioned path)
__device__ float g_w[3][DIM*DIM];        // conv-produced weights (+conv bias folded)
__device__ float g_qkv[3][ROWS*DIM];     // projected q,k,v

// ---------------------------------------------------------------------------
// Kernel 1: 9x9 VALID conv over template -> three 1024x1024 weight matrices.
// One shared template tile feeds all three filters.
// ---------------------------------------------------------------------------
__global__ void conv_kernel(const float* __restrict__ tmpl,
                            const float* __restrict__ cw0, const float* __restrict__ cb0,
                            const float* __restrict__ cw1, const float* __restrict__ cb1,
                            const float* __restrict__ cw2, const float* __restrict__ cb2) {
    __shared__ float sm[40][40];
    __shared__ float scw[3][81];
    const int tid = threadIdx.y * 32 + threadIdx.x;
    if (tid < 81) {
        scw[0][tid] = cw0[tid];
        scw[1][tid] = cw1[tid];
        scw[2][tid] = cw2[tid];
    }
    const int i0 = blockIdx.x * 32;   // input-col tile
    const int o0 = blockIdx.y * 32;   // output-row tile
    for (int idx = tid; idx < 40*40; idx += 256) {
        int r = idx / 40, c = idx % 40;
        sm[r][c] = tmpl[(size_t)(o0 + r) * TDIM + (i0 + c)];
    }
    __syncthreads();

    const int tx = threadIdx.x, ty = threadIdx.y;
    float acc0[4] = {0.f,0.f,0.f,0.f};
    float acc1[4] = {0.f,0.f,0.f,0.f};
    float acc2[4] = {0.f,0.f,0.f,0.f};
    #pragma unroll
    for (int u = 0; u < 9; u++) {
        #pragma unroll
        for (int v = 0; v < 9; v++) {
            const float w0 = scw[0][u*9+v];
            const float w1 = scw[1][u*9+v];
            const float w2 = scw[2][u*9+v];
            #pragma unroll
            for (int r = 0; r < 4; r++) {
                float t = sm[ty*4 + r + u][tx + v];
                acc0[r] += t * w0;
                acc1[r] += t * w1;
                acc2[r] += t * w2;
            }
        }
    }
    const float b0 = cb0[0], b1 = cb1[0], b2 = cb2[0];
    #pragma unroll
    for (int r = 0; r < 4; r++) {
        const size_t off = (size_t)(o0 + ty*4 + r) * DIM + i0 + tx;
        g_w[0][off] = acc0[r] + b0;
        g_w[1][off] = acc1[r] + b1;
        g_w[2][off] = acc2[r] + b2;
    }
}

// ---------------------------------------------------------------------------
// Kernel 2: projection GEMM (NT): Out[r,o] = sum_k A[r,k]*W[o,k] + lin_b[o].
// 64x64 block tile, BK=16, 256 threads, 4x4 micro-tile per thread.
// blockIdx.z selects q/k/v.
// ---------------------------------------------------------------------------
__global__ void proj_kernel(const float* __restrict__ qin, const float* __restrict__ kin,
                            const float* __restrict__ vin,
                            const float* __restrict__ bq, const float* __restrict__ bk,
                            const float* __restrict__ bv) {
    const int m = blockIdx.z;
    const float* __restrict__ A    = (m == 0) ? qin : (m == 1) ? kin : vin;
    const float* __restrict__ bias = (m == 0) ? bq  : (m == 1) ? bk  : bv;
    const float* __restrict__ W    = g_w[m];
    float* __restrict__ Out        = g_qkv[m];

    __shared__ float As[16][64];
    __shared__ float Ws[16][64];

    const int tid  = threadIdx.y * 16 + threadIdx.x;
    const int r0   = blockIdx.y * 64;
    const int c0   = blockIdx.x * 64;
    const int lrow = tid >> 2;        // 0..63
    const int lk   = (tid & 3) * 4;   // 0,4,8,12

    float c[4][4] = {};

    for (int kt = 0; kt < DIM; kt += 16) {
        const float4 av = *(const float4*)&A[(size_t)(r0 + lrow) * DIM + kt + lk];
        const float4 wv = *(const float4*)&W[(size_t)(c0 + lrow) * DIM + kt + lk];
        __syncthreads();
        As[lk+0][lrow] = av.x; As[lk+1][lrow] = av.y;
        As[lk+2][lrow] = av.z; As[lk+3][lrow] = av.w;
        Ws[lk+0][lrow] = wv.x; Ws[lk+1][lrow] = wv.y;
        Ws[lk+2][lrow] = wv.z; Ws[lk+3][lrow] = wv.w;
        __syncthreads();
        #pragma unroll
        for (int kk = 0; kk < 16; kk++) {
            const float4 a = *(const float4*)&As[kk][threadIdx.y * 4];
            const float4 b = *(const float4*)&Ws[kk][threadIdx.x * 4];
            c[0][0] += a.x*b.x; c[0][1] += a.x*b.y; c[0][2] += a.x*b.z; c[0][3] += a.x*b.w;
            c[1][0] += a.y*b.x; c[1][1] += a.y*b.y; c[1][2] += a.y*b.z; c[1][3] += a.y*b.w;
            c[2][0] += a.z*b.x; c[2][1] += a.z*b.y; c[2][2] += a.z*b.z; c[2][3] += a.z*b.w;
            c[3][0] += a.w*b.x; c[3][1] += a.w*b.y; c[3][2] += a.w*b.z; c[3][3] += a.w*b.w;
        }
    }

    const int orow = r0 + threadIdx.y * 4;
    const int ocol = c0 + threadIdx.x * 4;
    const float4 bb = *(const float4*)&bias[ocol];
    #pragma unroll
    for (int i = 0; i < 4; i++) {
        float4 res;
        res.x = c[i][0] + bb.x;
        res.y = c[i][1] + bb.y;
        res.z = c[i][2] + bb.z;
        res.w = c[i][3] + bb.w;
        *(float4*)&Out[(size_t)(orow + i) * DIM + ocol] = res;
    }
}

// ---------------------------------------------------------------------------
// Kernel 3: flash attention, fp32. One thread = one query row; 128 rows/block.
// KV streamed in 64-row tiles through shared memory; online softmax.
// Scores are near-one-hot (sigma~207) so __expf precision is more than enough.
// ---------------------------------------------------------------------------
__global__ void __launch_bounds__(128) attn_kernel(float* __restrict__ out) {
    const float* __restrict__ Q  = g_qkv[0];
    const float* __restrict__ Kp = g_qkv[1];
    const float* __restrict__ Vp = g_qkv[2];

    __shared__ float Ks[64][64];
    __shared__ float Vs[64][64];

    const int tid = threadIdx.x;
    const int qt  = blockIdx.x;           // 0..15  (128 q rows each)
    const int bh  = blockIdx.y;           // 0..31
    const int b   = bh & 1;
    const int h   = bh >> 1;

    const int qrow = qt * 128 + tid;
    const float* qptr = Q + ((size_t)(qrow * BATCH + b)) * DIM + h * HDIM;

    float qreg[64];
    #pragma unroll
    for (int d4 = 0; d4 < 16; d4++) {
        float4 t = *(const float4*)(qptr + d4 * 4);
        qreg[d4*4+0] = t.x * 0.125f;   // fold 1/sqrt(64) into q
        qreg[d4*4+1] = t.y * 0.125f;
        qreg[d4*4+2] = t.z * 0.125f;
        qreg[d4*4+3] = t.w * 0.125f;
    }
    float o[64];
    #pragma unroll
    for (int d = 0; d < 64; d++) o[d] = 0.f;
    float mval = -1e30f, l = 0.f;

    const size_t kvbase = (size_t)b * DIM + (size_t)h * HDIM;
    const size_t rstride = (size_t)BATCH * DIM;

    for (int kt = 0; kt < S_LEN / 64; kt++) {
        __syncthreads();
        const int s0 = kt * 64;
        for (int idx = tid; idx < 64 * 16; idx += 128) {
            const int j  = idx >> 4;
            const int d4 = (idx & 15) << 2;
            const size_t off = (size_t)(s0 + j) * rstride + kvbase + d4;
            *(float4*)&Ks[j][d4] = *(const float4*)(Kp + off);
            *(float4*)&Vs[j][d4] = *(const float4*)(Vp + off);
        }
        __syncthreads();

        #pragma unroll 1
        for (int ch = 0; ch < 4; ch++) {
            float s[16];
            #pragma unroll
            for (int jj = 0; jj < 16; jj++) {
                const int j = ch * 16 + jj;
                float acc = 0.f;
                #pragma unroll
                for (int d4 = 0; d4 < 16; d4++) {
                    const float4 kv = *(const float4*)&Ks[j][d4 << 2];
                    acc += qreg[d4*4+0] * kv.x;
                    acc += qreg[d4*4+1] * kv.y;
                    acc += qreg[d4*4+2] * kv.z;
                    acc += qreg[d4*4+3] * kv.w;
                }
                s[jj] = acc;
            }
            float mx = mval;
            #pragma unroll
            for (int jj = 0; jj < 16; jj++) mx = fmaxf(mx, s[jj]);
            if (mx > mval) {
                const float scale = __expf(mval - mx);
                mval = mx;
                l *= scale;
                #pragma unroll
                for (int d = 0; d < 64; d++) o[d] *= scale;
            }
            #pragma unroll
            for (int jj = 0; jj < 16; jj++) {
                const int j = ch * 16 + jj;
                const float p = __expf(s[jj] - mval);
                l += p;
                #pragma unroll
                for (int d4 = 0; d4 < 16; d4++) {
                    const float4 vv = *(const float4*)&Vs[j][d4 << 2];
                    o[d4*4+0] += p * vv.x;
                    o[d4*4+1] += p * vv.y;
                    o[d4*4+2] += p * vv.z;
                    o[d4*4+3] += p * vv.w;
                }
            }
        }
    }

    const float inv = 1.f / l;
    float* op = out + ((size_t)(qrow * BATCH + b)) * DIM + h * HDIM;
    #pragma unroll
    for (int d4 = 0; d4 < 16; d4++) {
        float4 res;
        res.x = o[d4*4+0] * inv;
        res.y = o[d4*4+1] * inv;
        res.z = o[d4*4+2] * inv;
        res.w = o[d4*4+3] * inv;
        *(float4*)(op + d4 * 4) = res;
    }
}

// ---------------------------------------------------------------------------
extern "C" void kernel_launch(void* const* d_in, const int* in_sizes, int n_in,
                              void* d_out, int out_size) {
    const float* query = (const float*)d_in[0];
    const float* key   = (const float*)d_in[1];
    const float* value = (const float*)d_in[2];
    const float* tmpl  = (const float*)d_in[3];
    const float* wq_cw = (const float*)d_in[4];
    const float* wq_cb = (const float*)d_in[5];
    const float* wq_b  = (const float*)d_in[6];
    const float* wk_cw = (const float*)d_in[7];
    const float* wk_cb = (const float*)d_in[8];
    const float* wk_b  = (const float*)d_in[9];
    const float* wv_cw = (const float*)d_in[10];
    const float* wv_cb = (const float*)d_in[11];
    const float* wv_b  = (const float*)d_in[12];
    float* out = (float*)d_out;

    conv_kernel<<<dim3(32, 32), dim3(32, 8)>>>(tmpl, wq_cw, wq_cb, wk_cw, wk_cb, wv_cw, wv_cb);
    proj_kernel<<<dim3(16, 64, 3), dim3(16, 16)>>>(query, key, value, wq_b, wk_b, wv_b);
    attn_kernel<<<dim3(16, 32), dim3(128)>>>(out);
}

// round 9
// speedup vs baseline: 1.0565x; 1.0009x over previous
#include <cuda_runtime.h>
#include <math.h>

#define S_LEN 2048
#define BATCH 2
#define DIM   1024
#define NHEAD 16
#define HDIM  64
#define TDIM  1032
#define ROWS  (S_LEN*BATCH)   // 4096

// Scratch (static device allocations are the sanctioned path)
__device__ float g_w[3][DIM*DIM];        // conv-produced weights (+conv bias folded)
__device__ float g_qkv[3][ROWS*DIM];     // projected q,k,v

// ---------------------------------------------------------------------------
// Kernel 1: 9x9 VALID conv over template -> three 1024x1024 weight matrices.
// One shared template tile feeds all three filters.
// ---------------------------------------------------------------------------
__global__ void conv_kernel(const float* __restrict__ tmpl,
                            const float* __restrict__ cw0, const float* __restrict__ cb0,
                            const float* __restrict__ cw1, const float* __restrict__ cb1,
                            const float* __restrict__ cw2, const float* __restrict__ cb2) {
    __shared__ float sm[40][40];
    __shared__ float scw[3][81];
    const int tid = threadIdx.y * 32 + threadIdx.x;
    if (tid < 81) {
        scw[0][tid] = cw0[tid];
        scw[1][tid] = cw1[tid];
        scw[2][tid] = cw2[tid];
    }
    const int i0 = blockIdx.x * 32;   // input-col tile
    const int o0 = blockIdx.y * 32;   // output-row tile
    for (int idx = tid; idx < 40*40; idx += 256) {
        int r = idx / 40, c = idx % 40;
        sm[r][c] = tmpl[(size_t)(o0 + r) * TDIM + (i0 + c)];
    }
    __syncthreads();

    const int tx = threadIdx.x, ty = threadIdx.y;
    float acc0[4] = {0.f,0.f,0.f,0.f};
    float acc1[4] = {0.f,0.f,0.f,0.f};
    float acc2[4] = {0.f,0.f,0.f,0.f};
    #pragma unroll
    for (int u = 0; u < 9; u++) {
        #pragma unroll
        for (int v = 0; v < 9; v++) {
            const float w0 = scw[0][u*9+v];
            const float w1 = scw[1][u*9+v];
            const float w2 = scw[2][u*9+v];
            #pragma unroll
            for (int r = 0; r < 4; r++) {
                float t = sm[ty*4 + r + u][tx + v];
                acc0[r] += t * w0;
                acc1[r] += t * w1;
                acc2[r] += t * w2;
            }
        }
    }
    const float b0 = cb0[0], b1 = cb1[0], b2 = cb2[0];
    #pragma unroll
    for (int r = 0; r < 4; r++) {
        const size_t off = (size_t)(o0 + ty*4 + r) * DIM + i0 + tx;
        g_w[0][off] = acc0[r] + b0;
        g_w[1][off] = acc1[r] + b1;
        g_w[2][off] = acc2[r] + b2;
    }
}

// ---------------------------------------------------------------------------
// Kernel 2: projection GEMM (NT): Out[r,o] = sum_k A[r,k]*W[o,k] + lin_b[o].
// 64x64 block tile, BK=16, 256 threads, 4x4 micro-tile per thread.
// blockIdx.z selects q/k/v.
// ---------------------------------------------------------------------------
__global__ void proj_kernel(const float* __restrict__ qin, const float* __restrict__ kin,
                            const float* __restrict__ vin,
                            const float* __restrict__ bq, const float* __restrict__ bk,
                            const float* __restrict__ bv) {
    const int m = blockIdx.z;
    const float* __restrict__ A    = (m == 0) ? qin : (m == 1) ? kin : vin;
    const float* __restrict__ bias = (m == 0) ? bq  : (m == 1) ? bk  : bv;
    const float* __restrict__ W    = g_w[m];
    float* __restrict__ Out        = g_qkv[m];

    __shared__ float As[16][64];
    __shared__ float Ws[16][64];

    const int tid  = threadIdx.y * 16 + threadIdx.x;
    const int r0   = blockIdx.y * 64;
    const int c0   = blockIdx.x * 64;
    const int lrow = tid >> 2;        // 0..63
    const int lk   = (tid & 3) * 4;   // 0,4,8,12

    float c[4][4] = {};

    for (int kt = 0; kt < DIM; kt += 16) {
        const float4 av = *(const float4*)&A[(size_t)(r0 + lrow) * DIM + kt + lk];
        const float4 wv = *(const float4*)&W[(size_t)(c0 + lrow) * DIM + kt + lk];
        __syncthreads();
        As[lk+0][lrow] = av.x; As[lk+1][lrow] = av.y;
        As[lk+2][lrow] = av.z; As[lk+3][lrow] = av.w;
        Ws[lk+0][lrow] = wv.x; Ws[lk+1][lrow] = wv.y;
        Ws[lk+2][lrow] = wv.z; Ws[lk+3][lrow] = wv.w;
        __syncthreads();
        #pragma unroll
        for (int kk = 0; kk < 16; kk++) {
            const float4 a = *(const float4*)&As[kk][threadIdx.y * 4];
            const float4 b = *(const float4*)&Ws[kk][threadIdx.x * 4];
            c[0][0] += a.x*b.x; c[0][1] += a.x*b.y; c[0][2] += a.x*b.z; c[0][3] += a.x*b.w;
            c[1][0] += a.y*b.x; c[1][1] += a.y*b.y; c[1][2] += a.y*b.z; c[1][3] += a.y*b.w;
            c[2][0] += a.z*b.x; c[2][1] += a.z*b.y; c[2][2] += a.z*b.z; c[2][3] += a.z*b.w;
            c[3][0] += a.w*b.x; c[3][1] += a.w*b.y; c[3][2] += a.w*b.z; c[3][3] += a.w*b.w;
        }
    }

    const int orow = r0 + threadIdx.y * 4;
    const int ocol = c0 + threadIdx.x * 4;
    const float4 bb = *(const float4*)&bias[ocol];
    #pragma unroll
    for (int i = 0; i < 4; i++) {
        float4 res;
        res.x = c[i][0] + bb.x;
        res.y = c[i][1] + bb.y;
        res.z = c[i][2] + bb.z;
        res.w = c[i][3] + bb.w;
        *(float4*)&Out[(size_t)(orow + i) * DIM + ocol] = res;
    }
}

// ---------------------------------------------------------------------------
// Kernel 3: flash attention, fp32. One thread = one query row; 128 rows/block.
// KV streamed in 64-row tiles through shared memory; online softmax.
// Scores are near-one-hot (sigma~207) so __expf precision is more than enough.
// ---------------------------------------------------------------------------
__global__ void __launch_bounds__(128) attn_kernel(float* __restrict__ out) {
    const float* __restrict__ Q  = g_qkv[0];
    const float* __restrict__ Kp = g_qkv[1];
    const float* __restrict__ Vp = g_qkv[2];

    __shared__ float Ks[64][64];
    __shared__ float Vs[64][64];

    const int tid = threadIdx.x;
    const int qt  = blockIdx.x;           // 0..15  (128 q rows each)
    const int bh  = blockIdx.y;           // 0..31
    const int b   = bh & 1;
    const int h   = bh >> 1;

    const int qrow = qt * 128 + tid;
    const float* qptr = Q + ((size_t)(qrow * BATCH + b)) * DIM + h * HDIM;

    float qreg[64];
    #pragma unroll
    for (int d4 = 0; d4 < 16; d4++) {
        float4 t = *(const float4*)(qptr + d4 * 4);
        qreg[d4*4+0] = t.x * 0.125f;   // fold 1/sqrt(64) into q
        qreg[d4*4+1] = t.y * 0.125f;
        qreg[d4*4+2] = t.z * 0.125f;
        qreg[d4*4+3] = t.w * 0.125f;
    }
    float o[64];
    #pragma unroll
    for (int d = 0; d < 64; d++) o[d] = 0.f;
    float mval = -1e30f, l = 0.f;

    const size_t kvbase = (size_t)b * DIM + (size_t)h * HDIM;
    const size_t rstride = (size_t)BATCH * DIM;

    for (int kt = 0; kt < S_LEN / 64; kt++) {
        __syncthreads();
        const int s0 = kt * 64;
        for (int idx = tid; idx < 64 * 16; idx += 128) {
            const int j  = idx >> 4;
            const int d4 = (idx & 15) << 2;
            const size_t off = (size_t)(s0 + j) * rstride + kvbase + d4;
            *(float4*)&Ks[j][d4] = *(const float4*)(Kp + off);
            *(float4*)&Vs[j][d4] = *(const float4*)(Vp + off);
        }
        __syncthreads();

        #pragma unroll 1
        for (int ch = 0; ch < 4; ch++) {
            float s[16];
            #pragma unroll
            for (int jj = 0; jj < 16; jj++) {
                const int j = ch * 16 + jj;
                float acc = 0.f;
                #pragma unroll
                for (int d4 = 0; d4 < 16; d4++) {
                    const float4 kv = *(const float4*)&Ks[j][d4 << 2];
                    acc += qreg[d4*4+0] * kv.x;
                    acc += qreg[d4*4+1] * kv.y;
                    acc += qreg[d4*4+2] * kv.z;
                    acc += qreg[d4*4+3] * kv.w;
                }
                s[jj] = acc;
            }
            float mx = mval;
            #pragma unroll
            for (int jj = 0; jj < 16; jj++) mx = fmaxf(mx, s[jj]);
            if (mx > mval) {
                const float scale = __expf(mval - mx);
                mval = mx;
                l *= scale;
                #pragma unroll
                for (int d = 0; d < 64; d++) o[d] *= scale;
            }
            #pragma unroll
            for (int jj = 0; jj < 16; jj++) {
                const int j = ch * 16 + jj;
                const float p = __expf(s[jj] - mval);
                l += p;
                #pragma unroll
                for (int d4 = 0; d4 < 16; d4++) {
                    const float4 vv = *(const float4*)&Vs[j][d4 << 2];
                    o[d4*4+0] += p * vv.x;
                    o[d4*4+1] += p * vv.y;
                    o[d4*4+2] += p * vv.z;
                    o[d4*4+3] += p * vv.w;
                }
            }
        }
    }

    const float inv = 1.f / l;
    float* op = out + ((size_t)(qrow * BATCH + b)) * DIM + h * HDIM;
    #pragma unroll
    for (int d4 = 0; d4 < 16; d4++) {
        float4 res;
        res.x = o[d4*4+0] * inv;
        res.y = o[d4*4+1] * inv;
        res.z = o[d4*4+2] * inv;
        res.w = o[d4*4+3] * inv;
        *(float4*)(op + d4 * 4) = res;
    }
}

// ---------------------------------------------------------------------------
extern "C" void kernel_launch(void* const* d_in, const int* in_sizes, int n_in,
                              void* d_out, int out_size) {
    const float* query = (const float*)d_in[0];
    const float* key   = (const float*)d_in[1];
    const float* value = (const float*)d_in[2];
    const float* tmpl  = (const float*)d_in[3];
    const float* wq_cw = (const float*)d_in[4];
    const float* wq_cb = (const float*)d_in[5];
    const float* wq_b  = (const float*)d_in[6];
    const float* wk_cw = (const float*)d_in[7];
    const float* wk_cb = (const float*)d_in[8];
    const float* wk_b  = (const float*)d_in[9];
    const float* wv_cw = (const float*)d_in[10];
    const float* wv_cb = (const float*)d_in[11];
    const float* wv_b  = (const float*)d_in[12];
    float* out = (float*)d_out;

    conv_kernel<<<dim3(32, 32), dim3(32, 8)>>>(tmpl, wq_cw, wq_cb, wk_cw, wk_cb, wv_cw, wv_cb);
    proj_kernel<<<dim3(16, 64, 3), dim3(16, 16)>>>(query, key, value, wq_b, wk_b, wv_b);
    attn_kernel<<<dim3(16, 32), dim3(128)>>>(out);
}